// round 15
// baseline (speedup 1.0000x reference)
#include <cuda_runtime.h>
#include <cuda_fp16.h>
#include <mma.h>
#include <stdint.h>
#include <math.h>

using namespace nvcuda;

#define N_NODES     4096
#define WORDS       128
#define IN_DIM      1024
#define HIDDEN      128
#define NUM_CLASSES 10
#define N_EDGES     65536
#define FINAL_DIM   896
#define CAP1        128
#define CAP2        768
#define XS_LD       72    // halves; 144 B rows — non-pow2, 16B-multiple
#define WS_LD       136   // halves; 272 B rows — non-pow2, 16B-multiple
#define SOUT_LD     132   // floats; 16B-multiple (wmma ldm requirement)

// ---------------------------------------------------------------------------
// Scratch (device globals — no runtime allocation allowed)
// ---------------------------------------------------------------------------
__device__ unsigned int g_Abits [N_NODES * WORDS];   // 2 MB
__device__ float g_d1[N_NODES];
__device__ float g_d2[N_NODES];
__device__ unsigned short g_idx1[N_NODES * CAP1];    // 1 MB
__device__ unsigned short g_idx2[N_NODES * CAP2];    // 6 MB
__device__ int   g_cnt1[N_NODES];
__device__ int   g_cnt2[N_NODES];
__device__ float g_R0[N_NODES * HIDDEN];             // 2 MB  fp32 (classifier)
__device__ float g_R1[N_NODES * 2 * HIDDEN];         // 4 MB  fp32 (classifier)
__device__ float g_R2[N_NODES * 4 * HIDDEN];         // 8 MB  fp32 (classifier)
// prescaled fp16 gather operands (row-major [node][col])
__device__ __half g_P0a[N_NODES * HIDDEN];           // 1 MB
__device__ __half g_P0b[N_NODES * HIDDEN];           // 1 MB
__device__ __half g_P1a[N_NODES * 2 * HIDDEN];       // 2 MB
__device__ __half g_P1b[N_NODES * 2 * HIDDEN];       // 2 MB
__device__ __half g_Wh[IN_DIM * HIDDEN];             // 256 KB fp16 embed weight

// ---------------------------------------------------------------------------
// merged: zero adjacency bitmap + fp16 weight convert (independent writes)
// ---------------------------------------------------------------------------
__global__ void k_init(const float* __restrict__ W) {
    int idx = blockIdx.x * blockDim.x + threadIdx.x;
    if (idx < N_NODES * WORDS) {
        g_Abits[idx] = 0u;
    } else {
        int i = idx - N_NODES * WORDS;
        if (i < IN_DIM * HIDDEN) g_Wh[i] = __float2half(W[i]);
    }
}

__global__ void k_scatter(const int* __restrict__ e) {
    int i = blockIdx.x * blockDim.x + threadIdx.x;
    if (i < N_EDGES) {
        int s = e[i]           & (N_NODES - 1);
        int d = e[N_EDGES + i] & (N_NODES - 1);
        atomicOr(&g_Abits[s * WORDS + (d >> 5)], 1u << (d & 31));
    }
}

// ---------------------------------------------------------------------------
// bitmap -> CSR (u16) + d = (deg+1e-8)^-1/2.  One warp per row.
// ---------------------------------------------------------------------------
__global__ void k_extract1() {
    int row  = blockIdx.x * 8 + (threadIdx.x >> 5);
    int lane = threadIdx.x & 31;
    const unsigned int* brow = g_Abits + (size_t)row * WORDS;

    unsigned w[4]; int c = 0;
    #pragma unroll
    for (int u = 0; u < 4; u++) { w[u] = brow[lane * 4 + u]; c += __popc(w[u]); }

    int inc = c;
    #pragma unroll
    for (int o = 1; o < 32; o <<= 1) {
        int t = __shfl_up_sync(0xffffffffu, inc, o);
        if (lane >= o) inc += t;
    }
    int total = __shfl_sync(0xffffffffu, inc, 31);
    int p = inc - c;

    unsigned short* dst = g_idx1 + (size_t)row * CAP1;
    #pragma unroll
    for (int u = 0; u < 4; u++) {
        unsigned word = w[u];
        int base = (lane * 4 + u) * 32;
        while (word) {
            int b = __ffs(word) - 1; word &= word - 1;
            if (p < CAP1) dst[p] = (unsigned short)(base + b);
            p++;
        }
    }
    if (lane == 31) {
        g_cnt1[row] = min(total, CAP1);
        g_d1[row]   = rsqrtf((float)total + 1e-8f);
    }
}

// ---------------------------------------------------------------------------
// 2-hop mask (union + special counts) fused with CSR extraction. 128 thr.
// ---------------------------------------------------------------------------
__global__ void k_twohop() {
    __shared__ unsigned s_out[WORDS];
    __shared__ unsigned short s_nb[CAP1];
    __shared__ int s_wtot[4];

    const int row  = blockIdx.x;
    const int tid  = threadIdx.x;   // 128
    const int wid  = tid >> 5;
    const int lane = tid & 31;
    const int nj   = g_cnt1[row];

    if (tid < nj) s_nb[tid] = g_idx1[(size_t)row * CAP1 + tid];
    __syncthreads();

    unsigned u = 0;
    for (int e = 0; e < nj; e++)
        u |= g_Abits[(size_t)s_nb[e] * WORDS + tid];
    unsigned my   = g_Abits[(size_t)row * WORDS + tid];
    unsigned diag = ((row >> 5) == tid) ? (1u << (row & 31)) : 0u;
    s_out[tid] = u & ~my & ~diag;
    __syncthreads();

    if (tid <= nj) {
        int k = (tid < nj) ? s_nb[tid] : row;
        int w = k >> 5, b = k & 31;
        int cnt = 0;
        for (int e = 0; e < nj; e++)
            cnt += (g_Abits[(size_t)s_nb[e] * WORDS + w] >> b) & 1;
        int abit = (g_Abits[(size_t)row * WORDS + w] >> b) & 1;
        int thr  = abit + (k == row ? 1 : 0);
        if (cnt > thr) atomicOr(&s_out[w], 1u << b);
    }
    __syncthreads();

    unsigned word = s_out[tid];
    int c = __popc(word);

    int inc = c;
    #pragma unroll
    for (int o = 1; o < 32; o <<= 1) {
        int t = __shfl_up_sync(0xffffffffu, inc, o);
        if (lane >= o) inc += t;
    }
    if (lane == 31) s_wtot[wid] = inc;
    __syncthreads();

    int wbase = 0;
    #pragma unroll
    for (int i = 0; i < 4; i++) if (i < wid) wbase += s_wtot[i];
    int total = s_wtot[0] + s_wtot[1] + s_wtot[2] + s_wtot[3];
    int p = wbase + inc - c;

    unsigned short* dst = g_idx2 + (size_t)row * CAP2;
    int basebit = tid * 32;
    while (word) {
        int b = __ffs(word) - 1; word &= word - 1;
        if (p < CAP2) dst[p] = (unsigned short)(basebit + b);
        p++;
    }
    if (tid == 0) {
        g_cnt2[row] = min(total, CAP2);
        g_d2[row]   = rsqrtf((float)total + 1e-8f);
    }
}

// ---------------------------------------------------------------------------
// half loads / accumulate helpers
// ---------------------------------------------------------------------------
__device__ __forceinline__ float4 load_h4(const __half* p) {
    uint2 u = *(const uint2*)p;
    float2 f0 = __half22float2(*(__half2*)&u.x);
    float2 f1 = __half22float2(*(__half2*)&u.y);
    return make_float4(f0.x, f0.y, f1.x, f1.y);
}
__device__ __forceinline__ void acc4(float4& a, float4 v) {
    a.x += v.x; a.y += v.y; a.z += v.z; a.w += v.w;
}
__device__ __forceinline__ void acc_u4(float* a, uint4 u) {
    float2 f0 = __half22float2(*(__half2*)&u.x);
    float2 f1 = __half22float2(*(__half2*)&u.y);
    float2 f2 = __half22float2(*(__half2*)&u.z);
    float2 f3 = __half22float2(*(__half2*)&u.w);
    a[0] += f0.x; a[1] += f0.y; a[2] += f1.x; a[3] += f1.y;
    a[4] += f2.x; a[5] += f2.y; a[6] += f3.x; a[7] += f3.y;
}

// ---------------------------------------------------------------------------
// Embed GEMM via wmma, padded smem strides (round-12, known good)
// ---------------------------------------------------------------------------
__global__ void __launch_bounds__(256) k_embed_mma(const float* __restrict__ X,
                                                  const float* __restrict__ bias) {
    extern __shared__ char dynsmem[];
    __half* Xs   = (__half*)dynsmem;
    __half* Wsh  = (__half*)(dynsmem + 64 * XS_LD * 2);
    float*  sOut = (float*)dynsmem;

    const int tid = threadIdx.x;
    const int wid = tid >> 5;
    const int wm  = wid >> 2;
    const int wn  = wid & 3;
    const int bm  = blockIdx.x * 64;

    wmma::fragment<wmma::accumulator, 16, 16, 16, float> c[2][2];
    #pragma unroll
    for (int mi = 0; mi < 2; mi++)
        #pragma unroll
        for (int ni = 0; ni < 2; ni++) wmma::fill_fragment(c[mi][ni], 0.f);

    for (int k0 = 0; k0 < IN_DIM; k0 += 64) {
        for (int i = tid; i < 64 * 32; i += 256) {
            int r = i >> 5, c2 = i & 31;
            float2 v = *(const float2*)(X + (size_t)(bm + r) * IN_DIM + k0 + c2 * 2);
            *(__half2*)(Xs + r * XS_LD + c2 * 2) = __floats2half2_rn(v.x, v.y);
        }
        for (int i = tid; i < 64 * 64; i += 256) {
            int r = i >> 6, c2 = i & 63;
            *(uint32_t*)(Wsh + r * WS_LD + c2 * 2) =
                *(const uint32_t*)(g_Wh + (size_t)(k0 + r) * 128 + c2 * 2);
        }
        __syncthreads();

        #pragma unroll
        for (int kk = 0; kk < 64; kk += 16) {
            wmma::fragment<wmma::matrix_a, 16, 16, 16, __half, wmma::row_major> a0, a1;
            wmma::fragment<wmma::matrix_b, 16, 16, 16, __half, wmma::row_major> b0, b1;
            wmma::load_matrix_sync(a0, Xs + (wm * 32 +  0) * XS_LD + kk, XS_LD);
            wmma::load_matrix_sync(a1, Xs + (wm * 32 + 16) * XS_LD + kk, XS_LD);
            wmma::load_matrix_sync(b0, Wsh + kk * WS_LD + wn * 32, WS_LD);
            wmma::load_matrix_sync(b1, Wsh + kk * WS_LD + wn * 32 + 16, WS_LD);
            wmma::mma_sync(c[0][0], a0, b0, c[0][0]);
            wmma::mma_sync(c[0][1], a0, b1, c[0][1]);
            wmma::mma_sync(c[1][0], a1, b0, c[1][0]);
            wmma::mma_sync(c[1][1], a1, b1, c[1][1]);
        }
        __syncthreads();
    }

    #pragma unroll
    for (int mi = 0; mi < 2; mi++)
        #pragma unroll
        for (int ni = 0; ni < 2; ni++)
            wmma::store_matrix_sync(sOut + (wm * 32 + mi * 16) * SOUT_LD + wn * 32 + ni * 16,
                                    c[mi][ni], SOUT_LD, wmma::mem_row_major);
    __syncthreads();

    for (int i = tid; i < 64 * 128; i += 256) {
        int r = i >> 7, cc = i & 127;
        float v = sOut[r * SOUT_LD + cc] + bias[cc];
        v = fmaxf(v, 0.f);
        int row = bm + r;
        g_R0 [(size_t)row * 128 + cc] = v;
        g_P0a[(size_t)row * 128 + cc] = __float2half(g_d1[row] * v);
        g_P0b[(size_t)row * 128 + cc] = __float2half(g_d2[row] * v);
    }
}

// ---------------------------------------------------------------------------
// Layer-1 propagation, phase-split: grid (4096, 2).
// y=0: A1 @ R0 (src P0a, idx1) -> cols [0,128);  y=1: A2 @ R0 (src P0b, idx2)
// -> cols [128,256). Block = 256 (8 warps); warp w owns e ≡ w (mod 8),
// lane owns 4 cols. No intra-block phase serialization.
// ---------------------------------------------------------------------------
__global__ void k_prop1() {
    __shared__ unsigned short s_idx[CAP2];
    __shared__ float s_red[8][HIDDEN];

    const int row = blockIdx.x;
    const int ph  = blockIdx.y;
    const int tid = threadIdx.x;
    const int w   = tid >> 5;
    const int l   = tid & 31;
    const int c4  = l * 4;

    const int n = ph ? g_cnt2[row] : g_cnt1[row];
    const unsigned short* gi = ph ? (g_idx2 + (size_t)row * CAP2)
                                  : (g_idx1 + (size_t)row * CAP1);
    const __half* src = ph ? g_P0b : g_P0a;
    const float dr = ph ? g_d2[row] : g_d1[row];
    const float d1r = g_d1[row], d2r = g_d2[row];

    for (int e = tid; e < n; e += 256) s_idx[e] = gi[e];
    __syncthreads();

    float4 a = {0.f, 0.f, 0.f, 0.f};
    int e = w;
    for (; e + 24 < n; e += 32) {
        float4 v0 = load_h4(src + (size_t)s_idx[e     ] * HIDDEN + c4);
        float4 v1 = load_h4(src + (size_t)s_idx[e +  8] * HIDDEN + c4);
        float4 v2 = load_h4(src + (size_t)s_idx[e + 16] * HIDDEN + c4);
        float4 v3 = load_h4(src + (size_t)s_idx[e + 24] * HIDDEN + c4);
        acc4(a, v0); acc4(a, v1); acc4(a, v2); acc4(a, v3);
    }
    for (; e < n; e += 8) acc4(a, load_h4(src + (size_t)s_idx[e] * HIDDEN + c4));
    *(float4*)&s_red[w][c4] = a;
    __syncthreads();

    if (tid < HIDDEN) {
        float s = 0.f;
        #pragma unroll
        for (int g = 0; g < 8; g++) s += s_red[g][tid];
        float val = dr * s;
        int col = ph * 128 + tid;
        g_R1 [(size_t)row * 256 + col] = val;
        g_P1a[(size_t)row * 256 + col] = __float2half(d1r * val);
        g_P1b[(size_t)row * 256 + col] = __float2half(d2r * val);
    }
}

// ---------------------------------------------------------------------------
// Layer-2 propagation, phase-split: grid (4096, 2).
// y=0: A1 @ R1 (src P1a, idx1) -> R2 cols [0,256);  y=1: A2 @ R1 (src P1b,
// idx2) -> R2 cols [256,512). Lane owns 8 of 256 cols (one LDG.128/neighbor).
// ---------------------------------------------------------------------------
__global__ void k_prop2() {
    __shared__ unsigned short s_idx[CAP2];
    __shared__ float s_red[8][2 * HIDDEN];   // 8 KB

    const int row = blockIdx.x;
    const int ph  = blockIdx.y;
    const int tid = threadIdx.x;
    const int w   = tid >> 5;
    const int l   = tid & 31;
    const int c8  = l * 8;

    const int n = ph ? g_cnt2[row] : g_cnt1[row];
    const unsigned short* gi = ph ? (g_idx2 + (size_t)row * CAP2)
                                  : (g_idx1 + (size_t)row * CAP1);
    const __half* src = ph ? g_P1b : g_P1a;
    const float dr = ph ? g_d2[row] : g_d1[row];

    for (int e = tid; e < n; e += 256) s_idx[e] = gi[e];
    __syncthreads();

    float a[8] = {0.f, 0.f, 0.f, 0.f, 0.f, 0.f, 0.f, 0.f};
    int e = w;
    for (; e + 24 < n; e += 32) {
        uint4 u0 = *(const uint4*)(src + (size_t)s_idx[e     ] * 256 + c8);
        uint4 u1 = *(const uint4*)(src + (size_t)s_idx[e +  8] * 256 + c8);
        uint4 u2 = *(const uint4*)(src + (size_t)s_idx[e + 16] * 256 + c8);
        uint4 u3 = *(const uint4*)(src + (size_t)s_idx[e + 24] * 256 + c8);
        acc_u4(a, u0); acc_u4(a, u1); acc_u4(a, u2); acc_u4(a, u3);
    }
    for (; e < n; e += 8)
        acc_u4(a, *(const uint4*)(src + (size_t)s_idx[e] * 256 + c8));
    *(float4*)&s_red[w][c8]     = *(float4*)&a[0];
    *(float4*)&s_red[w][c8 + 4] = *(float4*)&a[4];
    __syncthreads();

    {
        float s = 0.f;
        #pragma unroll
        for (int g = 0; g < 8; g++) s += s_red[g][tid];
        g_R2[(size_t)row * 512 + ph * 256 + tid] = dr * s;
    }
}

// ---------------------------------------------------------------------------
// classifier
// ---------------------------------------------------------------------------
__global__ void k_final(const float* __restrict__ Wc, const float* __restrict__ bc,
                        float* __restrict__ out) {
    int row  = blockIdx.x * 8 + (threadIdx.x >> 5);
    int lane = threadIdx.x & 31;

    float acc[NUM_CLASSES];
    #pragma unroll
    for (int cc = 0; cc < NUM_CLASSES; cc++) acc[cc] = 0.f;

    for (int j = lane; j < FINAL_DIM; j += 32) {
        float x;
        if (j < 128)       x = g_R0[(size_t)row * 128 + j];
        else if (j < 384)  x = g_R1[(size_t)row * 256 + (j - 128)];
        else               x = g_R2[(size_t)row * 512 + (j - 384)];
        const float* wr = Wc + (size_t)j * NUM_CLASSES;
        #pragma unroll
        for (int cc = 0; cc < NUM_CLASSES; cc++) acc[cc] += x * wr[cc];
    }
    #pragma unroll
    for (int cc = 0; cc < NUM_CLASSES; cc++)
        #pragma unroll
        for (int o = 16; o; o >>= 1) acc[cc] += __shfl_xor_sync(0xffffffffu, acc[cc], o);

    if (lane == 0) {
        #pragma unroll
        for (int cc = 0; cc < NUM_CLASSES; cc++)
            out[(size_t)row * NUM_CLASSES + cc] = acc[cc] + bc[cc];
    }
}

// ---------------------------------------------------------------------------
// launch — pure kernel launches
// ---------------------------------------------------------------------------
extern "C" void kernel_launch(void* const* d_in, const int* in_sizes, int n_in,
                              void* d_out, int out_size) {
    const float* X  = (const float*)d_in[0];
    const int*   E  = (const int*)d_in[1];          // int32 (jax x64 disabled)
    const float* We = (const float*)d_in[2];
    const float* be = (const float*)d_in[3];
    const float* Wc = (const float*)d_in[4];
    const float* bc = (const float*)d_in[5];
    float* out = (float*)d_out;

    const int SM_OPER = 64 * XS_LD * 2 + 64 * WS_LD * 2;   // 26624
    const int SM_OUT  = 64 * SOUT_LD * 4;                  // 33792
    const int SM_EMBED = SM_OPER > SM_OUT ? SM_OPER : SM_OUT;

    const int INIT_ELEMS = N_NODES * WORDS + IN_DIM * HIDDEN;
    k_init<<<(INIT_ELEMS + 255) / 256, 256>>>(We);
    k_scatter<<<N_EDGES / 256, 256>>>(E);
    k_extract1<<<N_NODES / 8, 256>>>();
    k_twohop<<<N_NODES, 128>>>();

    k_embed_mma<<<N_NODES / 64, 256, SM_EMBED>>>(X, be);

    k_prop1<<<dim3(N_NODES, 2), 256>>>();
    k_prop2<<<dim3(N_NODES, 2), 256>>>();

    k_final<<<N_NODES / 8, 256>>>(Wc, bc, out);
}

// round 16
// speedup vs baseline: 1.1245x; 1.1245x over previous
#include <cuda_runtime.h>
#include <cuda_fp16.h>
#include <mma.h>
#include <stdint.h>
#include <math.h>

using namespace nvcuda;

#define N_NODES     4096
#define WORDS       128
#define IN_DIM      1024
#define HIDDEN      128
#define NUM_CLASSES 10
#define N_EDGES     65536
#define FINAL_DIM   896
#define CAP1        128
#define CAP2        768
#define XS_LD       72    // halves; 144 B rows — non-pow2, 16B-multiple
#define WS_LD       136   // halves; 272 B rows — non-pow2, 16B-multiple
#define SOUT_LD     132   // floats; 16B-multiple (wmma ldm requirement)

// ---------------------------------------------------------------------------
// Scratch (device globals — no runtime allocation allowed)
// ---------------------------------------------------------------------------
__device__ unsigned int g_Abits [N_NODES * WORDS];   // 2 MB
__device__ float g_d1[N_NODES];
__device__ float g_d2[N_NODES];
__device__ unsigned short g_idx1[N_NODES * CAP1];    // 1 MB
__device__ unsigned short g_idx2[N_NODES * CAP2];    // 6 MB
__device__ int   g_cnt1[N_NODES];
__device__ int   g_cnt2[N_NODES];
__device__ float g_R0[N_NODES * HIDDEN];             // 2 MB  fp32 (classifier)
__device__ float g_R1[N_NODES * 2 * HIDDEN];         // 4 MB  fp32 (classifier)
__device__ float g_R2[N_NODES * 4 * HIDDEN];         // 8 MB  fp32 (classifier)
// prescaled fp16 gather operands (row-major [node][col])
__device__ __half g_P0a[N_NODES * HIDDEN];           // 1 MB
__device__ __half g_P0b[N_NODES * HIDDEN];           // 1 MB
__device__ __half g_P1a[N_NODES * 2 * HIDDEN];       // 2 MB
__device__ __half g_P1b[N_NODES * 2 * HIDDEN];       // 2 MB
__device__ __half g_Wh[IN_DIM * HIDDEN];             // 256 KB fp16 embed weight

// ---------------------------------------------------------------------------
// merged: zero adjacency bitmap + fp16 weight convert (independent writes)
// ---------------------------------------------------------------------------
__global__ void k_init(const float* __restrict__ W) {
    int idx = blockIdx.x * blockDim.x + threadIdx.x;
    if (idx < N_NODES * WORDS) {
        g_Abits[idx] = 0u;
    } else {
        int i = idx - N_NODES * WORDS;
        if (i < IN_DIM * HIDDEN) g_Wh[i] = __float2half(W[i]);
    }
}

__global__ void k_scatter(const int* __restrict__ e) {
    int i = blockIdx.x * blockDim.x + threadIdx.x;
    if (i < N_EDGES) {
        int s = e[i]           & (N_NODES - 1);
        int d = e[N_EDGES + i] & (N_NODES - 1);
        atomicOr(&g_Abits[s * WORDS + (d >> 5)], 1u << (d & 31));
    }
}

// ---------------------------------------------------------------------------
// bitmap -> CSR (u16) + d = (deg+1e-8)^-1/2.  One warp per row.
// ---------------------------------------------------------------------------
__global__ void k_extract1() {
    int row  = blockIdx.x * 8 + (threadIdx.x >> 5);
    int lane = threadIdx.x & 31;
    const unsigned int* brow = g_Abits + (size_t)row * WORDS;

    unsigned w[4]; int c = 0;
    #pragma unroll
    for (int u = 0; u < 4; u++) { w[u] = brow[lane * 4 + u]; c += __popc(w[u]); }

    int inc = c;
    #pragma unroll
    for (int o = 1; o < 32; o <<= 1) {
        int t = __shfl_up_sync(0xffffffffu, inc, o);
        if (lane >= o) inc += t;
    }
    int total = __shfl_sync(0xffffffffu, inc, 31);
    int p = inc - c;

    unsigned short* dst = g_idx1 + (size_t)row * CAP1;
    #pragma unroll
    for (int u = 0; u < 4; u++) {
        unsigned word = w[u];
        int base = (lane * 4 + u) * 32;
        while (word) {
            int b = __ffs(word) - 1; word &= word - 1;
            if (p < CAP1) dst[p] = (unsigned short)(base + b);
            p++;
        }
    }
    if (lane == 31) {
        g_cnt1[row] = min(total, CAP1);
        g_d1[row]   = rsqrtf((float)total + 1e-8f);
    }
}

// ---------------------------------------------------------------------------
// 2-hop mask (union + special counts) fused with CSR extraction. 128 thr.
// ---------------------------------------------------------------------------
__global__ void k_twohop() {
    __shared__ unsigned s_out[WORDS];
    __shared__ unsigned short s_nb[CAP1];
    __shared__ int s_wtot[4];

    const int row  = blockIdx.x;
    const int tid  = threadIdx.x;   // 128
    const int wid  = tid >> 5;
    const int lane = tid & 31;
    const int nj   = g_cnt1[row];

    if (tid < nj) s_nb[tid] = g_idx1[(size_t)row * CAP1 + tid];
    __syncthreads();

    unsigned u = 0;
    for (int e = 0; e < nj; e++)
        u |= g_Abits[(size_t)s_nb[e] * WORDS + tid];
    unsigned my   = g_Abits[(size_t)row * WORDS + tid];
    unsigned diag = ((row >> 5) == tid) ? (1u << (row & 31)) : 0u;
    s_out[tid] = u & ~my & ~diag;
    __syncthreads();

    if (tid <= nj) {
        int k = (tid < nj) ? s_nb[tid] : row;
        int w = k >> 5, b = k & 31;
        int cnt = 0;
        for (int e = 0; e < nj; e++)
            cnt += (g_Abits[(size_t)s_nb[e] * WORDS + w] >> b) & 1;
        int abit = (g_Abits[(size_t)row * WORDS + w] >> b) & 1;
        int thr  = abit + (k == row ? 1 : 0);
        if (cnt > thr) atomicOr(&s_out[w], 1u << b);
    }
    __syncthreads();

    unsigned word = s_out[tid];
    int c = __popc(word);

    int inc = c;
    #pragma unroll
    for (int o = 1; o < 32; o <<= 1) {
        int t = __shfl_up_sync(0xffffffffu, inc, o);
        if (lane >= o) inc += t;
    }
    if (lane == 31) s_wtot[wid] = inc;
    __syncthreads();

    int wbase = 0;
    #pragma unroll
    for (int i = 0; i < 4; i++) if (i < wid) wbase += s_wtot[i];
    int total = s_wtot[0] + s_wtot[1] + s_wtot[2] + s_wtot[3];
    int p = wbase + inc - c;

    unsigned short* dst = g_idx2 + (size_t)row * CAP2;
    int basebit = tid * 32;
    while (word) {
        int b = __ffs(word) - 1; word &= word - 1;
        if (p < CAP2) dst[p] = (unsigned short)(basebit + b);
        p++;
    }
    if (tid == 0) {
        g_cnt2[row] = min(total, CAP2);
        g_d2[row]   = rsqrtf((float)total + 1e-8f);
    }
}

// ---------------------------------------------------------------------------
// half loads / accumulate helpers
// ---------------------------------------------------------------------------
__device__ __forceinline__ float4 load_h4(const __half* p) {
    uint2 u = *(const uint2*)p;
    float2 f0 = __half22float2(*(__half2*)&u.x);
    float2 f1 = __half22float2(*(__half2*)&u.y);
    return make_float4(f0.x, f0.y, f1.x, f1.y);
}
__device__ __forceinline__ void acc4(float4& a, float4 v) {
    a.x += v.x; a.y += v.y; a.z += v.z; a.w += v.w;
}
__device__ __forceinline__ void acc_u4(float* a, uint4 u) {
    float2 f0 = __half22float2(*(__half2*)&u.x);
    float2 f1 = __half22float2(*(__half2*)&u.y);
    float2 f2 = __half22float2(*(__half2*)&u.z);
    float2 f3 = __half22float2(*(__half2*)&u.w);
    a[0] += f0.x; a[1] += f0.y; a[2] += f1.x; a[3] += f1.y;
    a[4] += f2.x; a[5] += f2.y; a[6] += f3.x; a[7] += f3.y;
}

// ---------------------------------------------------------------------------
// Embed GEMM via wmma, padded smem strides. Writes R0 ONLY (prescale split
// off so this kernel has no dependency on graph prep -> runs on stream 2).
// ---------------------------------------------------------------------------
__global__ void __launch_bounds__(256) k_embed_mma(const float* __restrict__ X,
                                                  const float* __restrict__ bias) {
    extern __shared__ char dynsmem[];
    __half* Xs   = (__half*)dynsmem;
    __half* Wsh  = (__half*)(dynsmem + 64 * XS_LD * 2);
    float*  sOut = (float*)dynsmem;

    const int tid = threadIdx.x;
    const int wid = tid >> 5;
    const int wm  = wid >> 2;
    const int wn  = wid & 3;
    const int bm  = blockIdx.x * 64;

    wmma::fragment<wmma::accumulator, 16, 16, 16, float> c[2][2];
    #pragma unroll
    for (int mi = 0; mi < 2; mi++)
        #pragma unroll
        for (int ni = 0; ni < 2; ni++) wmma::fill_fragment(c[mi][ni], 0.f);

    for (int k0 = 0; k0 < IN_DIM; k0 += 64) {
        for (int i = tid; i < 64 * 32; i += 256) {
            int r = i >> 5, c2 = i & 31;
            float2 v = *(const float2*)(X + (size_t)(bm + r) * IN_DIM + k0 + c2 * 2);
            *(__half2*)(Xs + r * XS_LD + c2 * 2) = __floats2half2_rn(v.x, v.y);
        }
        for (int i = tid; i < 64 * 64; i += 256) {
            int r = i >> 6, c2 = i & 63;
            *(uint32_t*)(Wsh + r * WS_LD + c2 * 2) =
                *(const uint32_t*)(g_Wh + (size_t)(k0 + r) * 128 + c2 * 2);
        }
        __syncthreads();

        #pragma unroll
        for (int kk = 0; kk < 64; kk += 16) {
            wmma::fragment<wmma::matrix_a, 16, 16, 16, __half, wmma::row_major> a0, a1;
            wmma::fragment<wmma::matrix_b, 16, 16, 16, __half, wmma::row_major> b0, b1;
            wmma::load_matrix_sync(a0, Xs + (wm * 32 +  0) * XS_LD + kk, XS_LD);
            wmma::load_matrix_sync(a1, Xs + (wm * 32 + 16) * XS_LD + kk, XS_LD);
            wmma::load_matrix_sync(b0, Wsh + kk * WS_LD + wn * 32, WS_LD);
            wmma::load_matrix_sync(b1, Wsh + kk * WS_LD + wn * 32 + 16, WS_LD);
            wmma::mma_sync(c[0][0], a0, b0, c[0][0]);
            wmma::mma_sync(c[0][1], a0, b1, c[0][1]);
            wmma::mma_sync(c[1][0], a1, b0, c[1][0]);
            wmma::mma_sync(c[1][1], a1, b1, c[1][1]);
        }
        __syncthreads();
    }

    #pragma unroll
    for (int mi = 0; mi < 2; mi++)
        #pragma unroll
        for (int ni = 0; ni < 2; ni++)
            wmma::store_matrix_sync(sOut + (wm * 32 + mi * 16) * SOUT_LD + wn * 32 + ni * 16,
                                    c[mi][ni], SOUT_LD, wmma::mem_row_major);
    __syncthreads();

    for (int i = tid; i < 64 * 128; i += 256) {
        int r = i >> 7, cc = i & 127;
        float v = sOut[r * SOUT_LD + cc] + bias[cc];
        v = fmaxf(v, 0.f);
        g_R0[(size_t)(bm + r) * 128 + cc] = v;
    }
}

// ---------------------------------------------------------------------------
// prescale: P0a = fp16(d1*R0), P0b = fp16(d2*R0)  (identical math to the old
// fused epilogue — rounds the same fp32 product).  524288 elements.
// ---------------------------------------------------------------------------
__global__ void k_prescale0() {
    int i = blockIdx.x * 256 + threadIdx.x;
    int row = i >> 7;
    float v = g_R0[i];
    g_P0a[i] = __float2half(g_d1[row] * v);
    g_P0b[i] = __float2half(g_d2[row] * v);
}

// ---------------------------------------------------------------------------
// Layer-1 propagation (fused a1+a2). Block=256 (8 warps), row per block.
// (round-14 version, best known)
// ---------------------------------------------------------------------------
__global__ void k_prop1() {
    __shared__ unsigned short s_i1[CAP1];
    __shared__ unsigned short s_i2[CAP2];
    __shared__ float s_red[8][HIDDEN];

    const int row = blockIdx.x;
    const int tid = threadIdx.x;
    const int w   = tid >> 5;
    const int l   = tid & 31;
    const int c4  = l * 4;
    const int n1  = g_cnt1[row];
    const int n2  = g_cnt2[row];
    const float d1r = g_d1[row], d2r = g_d2[row];

    for (int e = tid; e < n1; e += 256) s_i1[e] = g_idx1[(size_t)row * CAP1 + e];
    for (int e = tid; e < n2; e += 256) s_i2[e] = g_idx2[(size_t)row * CAP2 + e];
    __syncthreads();

    // ---- phase A : A1 @ R0 ----
    {
        float4 a = {0.f, 0.f, 0.f, 0.f};
        int e = w;
        for (; e + 24 < n1; e += 32) {
            float4 v0 = load_h4(g_P0a + (size_t)s_i1[e     ] * HIDDEN + c4);
            float4 v1 = load_h4(g_P0a + (size_t)s_i1[e +  8] * HIDDEN + c4);
            float4 v2 = load_h4(g_P0a + (size_t)s_i1[e + 16] * HIDDEN + c4);
            float4 v3 = load_h4(g_P0a + (size_t)s_i1[e + 24] * HIDDEN + c4);
            acc4(a, v0); acc4(a, v1); acc4(a, v2); acc4(a, v3);
        }
        for (; e < n1; e += 8) acc4(a, load_h4(g_P0a + (size_t)s_i1[e] * HIDDEN + c4));
        *(float4*)&s_red[w][c4] = a;
    }
    __syncthreads();
    if (tid < HIDDEN) {
        float s = 0.f;
        #pragma unroll
        for (int g = 0; g < 8; g++) s += s_red[g][tid];
        float val = d1r * s;
        g_R1 [(size_t)row * 256 + tid] = val;
        g_P1a[(size_t)row * 256 + tid] = __float2half(d1r * val);
        g_P1b[(size_t)row * 256 + tid] = __float2half(d2r * val);
    }
    __syncthreads();

    // ---- phase B : A2 @ R0 ----
    {
        float4 a = {0.f, 0.f, 0.f, 0.f};
        int e = w;
        for (; e + 24 < n2; e += 32) {
            float4 v0 = load_h4(g_P0b + (size_t)s_i2[e     ] * HIDDEN + c4);
            float4 v1 = load_h4(g_P0b + (size_t)s_i2[e +  8] * HIDDEN + c4);
            float4 v2 = load_h4(g_P0b + (size_t)s_i2[e + 16] * HIDDEN + c4);
            float4 v3 = load_h4(g_P0b + (size_t)s_i2[e + 24] * HIDDEN + c4);
            acc4(a, v0); acc4(a, v1); acc4(a, v2); acc4(a, v3);
        }
        for (; e < n2; e += 8) acc4(a, load_h4(g_P0b + (size_t)s_i2[e] * HIDDEN + c4));
        *(float4*)&s_red[w][c4] = a;
    }
    __syncthreads();
    if (tid < HIDDEN) {
        float s = 0.f;
        #pragma unroll
        for (int g = 0; g < 8; g++) s += s_red[g][tid];
        float val = d2r * s;
        g_R1 [(size_t)row * 256 + 128 + tid] = val;
        g_P1a[(size_t)row * 256 + 128 + tid] = __float2half(d1r * val);
        g_P1b[(size_t)row * 256 + 128 + tid] = __float2half(d2r * val);
    }
}

// ---------------------------------------------------------------------------
// Layer-2 propagation (fused a1+a2). Block=256 (8 warps), row per block.
// Lane owns 8 of 256 cols -> one LDG.128 per neighbor. (round-14 version)
// ---------------------------------------------------------------------------
__global__ void k_prop2() {
    __shared__ unsigned short s_i1[CAP1];
    __shared__ unsigned short s_i2[CAP2];
    __shared__ float s_red[8][2 * HIDDEN];   // 8 KB

    const int row = blockIdx.x;
    const int tid = threadIdx.x;
    const int w   = tid >> 5;
    const int l   = tid & 31;
    const int c8  = l * 8;
    const int n1  = g_cnt1[row];
    const int n2  = g_cnt2[row];
    const float d1r = g_d1[row], d2r = g_d2[row];

    for (int e = tid; e < n1; e += 256) s_i1[e] = g_idx1[(size_t)row * CAP1 + e];
    for (int e = tid; e < n2; e += 256) s_i2[e] = g_idx2[(size_t)row * CAP2 + e];
    __syncthreads();

    // ---- phase A : A1 @ R1  (source P1a) ----
    {
        float a[8] = {0.f, 0.f, 0.f, 0.f, 0.f, 0.f, 0.f, 0.f};
        int e = w;
        for (; e + 24 < n1; e += 32) {
            uint4 u0 = *(const uint4*)(g_P1a + (size_t)s_i1[e     ] * 256 + c8);
            uint4 u1 = *(const uint4*)(g_P1a + (size_t)s_i1[e +  8] * 256 + c8);
            uint4 u2 = *(const uint4*)(g_P1a + (size_t)s_i1[e + 16] * 256 + c8);
            uint4 u3 = *(const uint4*)(g_P1a + (size_t)s_i1[e + 24] * 256 + c8);
            acc_u4(a, u0); acc_u4(a, u1); acc_u4(a, u2); acc_u4(a, u3);
        }
        for (; e < n1; e += 8)
            acc_u4(a, *(const uint4*)(g_P1a + (size_t)s_i1[e] * 256 + c8));
        *(float4*)&s_red[w][c8]     = *(float4*)&a[0];
        *(float4*)&s_red[w][c8 + 4] = *(float4*)&a[4];
    }
    __syncthreads();
    {
        float s = 0.f;
        #pragma unroll
        for (int g = 0; g < 8; g++) s += s_red[g][tid];
        g_R2[(size_t)row * 512 + tid] = d1r * s;
    }
    __syncthreads();

    // ---- phase B : A2 @ R1  (source P1b) ----
    {
        float a[8] = {0.f, 0.f, 0.f, 0.f, 0.f, 0.f, 0.f, 0.f};
        int e = w;
        for (; e + 24 < n2; e += 32) {
            uint4 u0 = *(const uint4*)(g_P1b + (size_t)s_i2[e     ] * 256 + c8);
            uint4 u1 = *(const uint4*)(g_P1b + (size_t)s_i2[e +  8] * 256 + c8);
            uint4 u2 = *(const uint4*)(g_P1b + (size_t)s_i2[e + 16] * 256 + c8);
            uint4 u3 = *(const uint4*)(g_P1b + (size_t)s_i2[e + 24] * 256 + c8);
            acc_u4(a, u0); acc_u4(a, u1); acc_u4(a, u2); acc_u4(a, u3);
        }
        for (; e < n2; e += 8)
            acc_u4(a, *(const uint4*)(g_P1b + (size_t)s_i2[e] * 256 + c8));
        *(float4*)&s_red[w][c8]     = *(float4*)&a[0];
        *(float4*)&s_red[w][c8 + 4] = *(float4*)&a[4];
    }
    __syncthreads();
    {
        float s = 0.f;
        #pragma unroll
        for (int g = 0; g < 8; g++) s += s_red[g][tid];
        g_R2[(size_t)row * 512 + 256 + tid] = d2r * s;
    }
}

// ---------------------------------------------------------------------------
// classifier
// ---------------------------------------------------------------------------
__global__ void k_final(const float* __restrict__ Wc, const float* __restrict__ bc,
                        float* __restrict__ out) {
    int row  = blockIdx.x * 8 + (threadIdx.x >> 5);
    int lane = threadIdx.x & 31;

    float acc[NUM_CLASSES];
    #pragma unroll
    for (int cc = 0; cc < NUM_CLASSES; cc++) acc[cc] = 0.f;

    for (int j = lane; j < FINAL_DIM; j += 32) {
        float x;
        if (j < 128)       x = g_R0[(size_t)row * 128 + j];
        else if (j < 384)  x = g_R1[(size_t)row * 256 + (j - 128)];
        else               x = g_R2[(size_t)row * 512 + (j - 384)];
        const float* wr = Wc + (size_t)j * NUM_CLASSES;
        #pragma unroll
        for (int cc = 0; cc < NUM_CLASSES; cc++) acc[cc] += x * wr[cc];
    }
    #pragma unroll
    for (int cc = 0; cc < NUM_CLASSES; cc++)
        #pragma unroll
        for (int o = 16; o; o >>= 1) acc[cc] += __shfl_xor_sync(0xffffffffu, acc[cc], o);

    if (lane == 0) {
        #pragma unroll
        for (int cc = 0; cc < NUM_CLASSES; cc++)
            out[(size_t)row * NUM_CLASSES + cc] = acc[cc] + bc[cc];
    }
}

// ---------------------------------------------------------------------------
// launch — kernels + graph-capturable fork/join (embed overlaps graph prep)
// ---------------------------------------------------------------------------
extern "C" void kernel_launch(void* const* d_in, const int* in_sizes, int n_in,
                              void* d_out, int out_size) {
    const float* X  = (const float*)d_in[0];
    const int*   E  = (const int*)d_in[1];          // int32 (jax x64 disabled)
    const float* We = (const float*)d_in[2];
    const float* be = (const float*)d_in[3];
    const float* Wc = (const float*)d_in[4];
    const float* bc = (const float*)d_in[5];
    float* out = (float*)d_out;

    // one-time resources (first call is the uncaptured correctness run)
    static cudaStream_t s2 = nullptr;
    static cudaEvent_t evFork = nullptr, evJoin = nullptr;
    if (s2 == nullptr) {
        cudaStreamCreateWithFlags(&s2, cudaStreamNonBlocking);
        cudaEventCreateWithFlags(&evFork, cudaEventDisableTiming);
        cudaEventCreateWithFlags(&evJoin, cudaEventDisableTiming);
    }

    const int SM_OPER = 64 * XS_LD * 2 + 64 * WS_LD * 2;   // 26624
    const int SM_OUT  = 64 * SOUT_LD * 4;                  // 33792
    const int SM_EMBED = SM_OPER > SM_OUT ? SM_OPER : SM_OUT;

    const int INIT_ELEMS = N_NODES * WORDS + IN_DIM * HIDDEN;
    k_init<<<(INIT_ELEMS + 255) / 256, 256>>>(We);

    // fork: embed (depends only on X + g_Wh from k_init) on stream s2
    cudaEventRecord(evFork, 0);
    cudaStreamWaitEvent(s2, evFork, 0);
    k_embed_mma<<<N_NODES / 64, 256, SM_EMBED, s2>>>(X, be);
    cudaEventRecord(evJoin, s2);

    // graph prep chain on default stream (concurrent with embed)
    k_scatter<<<N_EDGES / 256, 256>>>(E);
    k_extract1<<<N_NODES / 8, 256>>>();
    k_twohop<<<N_NODES, 128>>>();

    // join: prescale needs R0 (embed) + d1/d2 (extract1/twohop)
    cudaStreamWaitEvent(0, evJoin, 0);
    k_prescale0<<<N_NODES * HIDDEN / 256, 256>>>();

    k_prop1<<<N_NODES, 256>>>();
    k_prop2<<<N_NODES, 256>>>();

    k_final<<<N_NODES / 8, 256>>>(Wc, bc, out);
}